// round 15
// baseline (speedup 1.0000x reference)
#include <cuda_runtime.h>

// Problem constants (STGNN_91242285236402): B=8, T=16, N=64, F=16, H=128
#define Bc 8
#define Tc 16
#define Nc 64
#define Fc 16
#define Hc 128
#define BN (Bc * Nc)   // 512
#define GRID 128
#define NTHR 256

// Folded-weight scratch (allocation-free, 16B-aligned for float4 loads)
__device__ __align__(16) float g_Ms[Hc * Fc];   // M_s[k][f] = sum_h W1s[k][h]*Wg[h][f]
__device__ __align__(16) float g_Mt[Hc * Fc];   // M_t[k][f] = sum_h W1t[k][h]*Wg[h][f]
__device__ __align__(16) float g_ca[Hc];        // b1[k] + W1s[k]·bg
__device__ __align__(16) float g_ct[Hc];        // W1t[k]·bg
__device__ __align__(16) float g_wvec[Hc];      // Wgcn.T @ Wp
__device__ unsigned g_bar = 0;                  // arrival counter (monotonic)
struct Flag { unsigned f; unsigned pad[31]; };  // 128B-strided release flags
__device__ Flag g_flag[GRID];                   // per-block, own L2 line each

__device__ __forceinline__ float dot16v(const float4* a, const float4* b)
{
    float p0 = a[0].x*b[0].x + a[0].y*b[0].y + a[0].z*b[0].z + a[0].w*b[0].w;
    float p1 = a[1].x*b[1].x + a[1].y*b[1].y + a[1].z*b[1].z + a[1].w*b[1].w;
    float p2 = a[2].x*b[2].x + a[2].y*b[2].y + a[2].z*b[2].z + a[2].w*b[2].w;
    float p3 = a[3].x*b[3].x + a[3].y*b[3].y + a[3].z*b[3].z + a[3].w*b[3].w;
    return (p0 + p1) + (p2 + p3);
}

// ---------------------------------------------------------------------------
// One fused kernel, 128 blocks x 256 threads (all co-resident).
// PRE-arrive (block i): stage x[b]; compute row k=i of M_s/M_t (+ca/ct/wvec).
// ARRIVE: monotonic ticket; 128th arriver fans out per-block release flags.
// HIDDEN: node rows (lp input); w2 stage; pr init; xa register preload.
// WAIT: poll own flag (contention-free), acquire.
// POST (b=i>>4, g=i&15): stage M_t+ct; a from M_s; lp from wvec;
//   bt[k][t] for all t locally (16-MAC dots) -> smem; dense edge loop:
//     ew(s,t) = b2 + sum_k relu(a[s,k]+bt[k,t])*W2[k], e = s*63+(t-(t>s))
//     pressures[b,t] += ew*lp[s]
// ---------------------------------------------------------------------------
__global__ void __launch_bounds__(NTHR, 1) kfused(
    const float* __restrict__ x,   const float* __restrict__ Wg,
    const float* __restrict__ bg,  const float* __restrict__ W1,
    const float* __restrict__ b1,  const float* __restrict__ W2,
    const float* __restrict__ b2,  const float* __restrict__ Wgcn,
    const float* __restrict__ bgcn,const float* __restrict__ Wp,
    const float* __restrict__ bp,  float* __restrict__ out, int E)
{
    __shared__ union {
        float bt4[32][Nc][4];                 // [k>>2][t][k&3]  (32KB, post)
        struct {
            float pm[2][8][17];               // M partials (padded)
            float node[4][Hc];                // node rows for lp
        } pre;
    } u;
    __shared__ float x_sh[Nc * Fc];           // 4KB  [n][f]
    __shared__ float a_sh[4][Hc];             // 2KB
    __shared__ float Mt_sh[Hc * Fc];          // 8KB  [k][f]
    __shared__ float ct_sh[Hc];
    __shared__ float w2_sh[Hc];
    __shared__ float lp_sh[4];
    __shared__ float pr_sh[Nc];
    __shared__ unsigned s_target;

    const int tid = threadIdx.x;
    const int i = blockIdx.x;
    const int b = i >> 4, g = i & 15;
    const int k = i;                          // this block's M row
    const int lane = tid & 31, w = tid >> 5;

    // ================= PRE-ARRIVE =================
    // stage x[b, T-1] (256 float4, coalesced)
    {
        const float4* xs = (const float4*)(x + (size_t)((b * Tc + (Tc - 1)) * Nc) * Fc);
        ((float4*)x_sh)[tid] = __ldg(xs + tid);
    }
    if (i < Bc && tid < Nc) out[i * Nc + tid] = __ldg(bp);   // pressures init

    // M partials: side = tid>>7, f = tid&15, hg = (tid>>4)&7 ; W1 via float4
    {
        const int side = tid >> 7;
        const int f = tid & 15;
        const int hg = (tid >> 4) & 7;
        const float4* w1r4 = (const float4*)(W1 + k * (2 * Hc) + side * Hc + hg * 16);
        float4 wa = __ldg(w1r4 + 0), wb = __ldg(w1r4 + 1);
        float4 wc = __ldg(w1r4 + 2), wd = __ldg(w1r4 + 3);
        const float* wgp = Wg + (hg * 16) * Fc + f;
        float s0 = wa.x*__ldg(wgp+ 0*Fc) + wa.y*__ldg(wgp+ 1*Fc)
                 + wa.z*__ldg(wgp+ 2*Fc) + wa.w*__ldg(wgp+ 3*Fc);
        float s1 = wb.x*__ldg(wgp+ 4*Fc) + wb.y*__ldg(wgp+ 5*Fc)
                 + wb.z*__ldg(wgp+ 6*Fc) + wb.w*__ldg(wgp+ 7*Fc);
        float s2 = wc.x*__ldg(wgp+ 8*Fc) + wc.y*__ldg(wgp+ 9*Fc)
                 + wc.z*__ldg(wgp+10*Fc) + wc.w*__ldg(wgp+11*Fc);
        float s3 = wd.x*__ldg(wgp+12*Fc) + wd.y*__ldg(wgp+13*Fc)
                 + wd.z*__ldg(wgp+14*Fc) + wd.w*__ldg(wgp+15*Fc);
        u.pre.pm[side][hg][f] = (s0 + s1) + (s2 + s3);
    }
    __syncthreads();

    // finishing: warp0 M-reduce; warp2 ca/ct; warp3 wvec[k]
    if (w == 0) {
        int side = lane >> 4, f = lane & 15;
        float m = 0.f;
        #pragma unroll
        for (int hg = 0; hg < 8; hg++) m += u.pre.pm[side][hg][f];
        if (side == 0) g_Ms[k * 16 + f] = m;
        else           g_Mt[k * 16 + f] = m;
    } else if (w == 2) {
        int side = lane >> 4;
        int h0 = (lane & 15) * 8;
        const float* w1r = W1 + k * (2 * Hc) + side * Hc + h0;
        float s = 0.f;
        #pragma unroll
        for (int e = 0; e < 8; e++) s += __ldg(&bg[h0 + e]) * __ldg(w1r + e);
        s += __shfl_xor_sync(0xffffffffu, s, 1);
        s += __shfl_xor_sync(0xffffffffu, s, 2);
        s += __shfl_xor_sync(0xffffffffu, s, 4);
        s += __shfl_xor_sync(0xffffffffu, s, 8);
        if ((lane & 15) == 0) {
            if (side == 0) g_ca[k] = s + __ldg(&b1[k]);
            else           g_ct[k] = s;
        }
    } else if (w == 3) {
        float s = 0.f;
        #pragma unroll
        for (int e = 0; e < 4; e++)
            s += __ldg(&Wp[lane * 4 + e]) * __ldg(&Wgcn[(lane * 4 + e) * Hc + k]);
        #pragma unroll
        for (int o = 16; o; o >>= 1) s += __shfl_xor_sync(0xffffffffu, s, o);
        if (lane == 0) g_wvec[k] = s;
    }

    // ---- ARRIVE (ticket) + fan-out release by the 128th arriver
    __syncthreads();                          // all cross-block stores issued
    if (tid == 0) {
        __threadfence();                      // publish before arrival
        unsigned v = atomicAdd(&g_bar, 1u);
        unsigned rel = (v >> 7) + 1u;         // this launch's release epoch
        s_target = rel;
        if ((v & (GRID - 1u)) == GRID - 1u) { // last arriver: fan out
            __threadfence();
            #pragma unroll 4
            for (int r = 0; r < GRID; r++)
                *(volatile unsigned*)&g_flag[r].f = rel;
        }
    }

    // ======== HIDDEN independent work (between arrive and wait) ========
    // node rows (for lp): 4 rows x 128 h, 2 outputs/thread
    #pragma unroll
    for (int it = 0; it < 2; it++) {
        int idx = tid + it * NTHR;
        int rl = idx >> 7, h = idx & 127;
        const float4* wg4 = (const float4*)(Wg + h * Fc);
        float4 wv[4] = { __ldg(wg4), __ldg(wg4+1), __ldg(wg4+2), __ldg(wg4+3) };
        const float4* xr = (const float4*)(x_sh + (g * 4 + rl) * Fc);
        float4 xv[4] = { xr[0], xr[1], xr[2], xr[3] };
        u.pre.node[rl][h] = __ldg(&bg[h]) + dot16v(xv, wv);
    }
    if (tid < Hc) w2_sh[tid] = __ldg(&W2[tid]);
    if (tid < Nc) pr_sh[tid] = 0.f;
    // xa preload for bt phase (persists in registers across the wait)
    float4 xa[2][4];
    #pragma unroll
    for (int th = 0; th < 2; th++)
        #pragma unroll
        for (int jj = 0; jj < 4; jj++)
            xa[th][jj] = *(const float4*)(x_sh + (th * 32 + lane) * Fc + jj * 4);

    // ---- WAIT: poll own flag (contention-free)
    __syncthreads();                          // s_target visible; hidden done
    if (tid == 0) {
        volatile unsigned* p = &g_flag[i].f;
        while (*p < s_target) __nanosleep(32);
        __threadfence();                      // acquire
    }
    __syncthreads();

    // ================= POST =================
    // stage M_t (512 float4) + ct
    {
        const float4* src = (const float4*)g_Mt;
        ((float4*)Mt_sh)[tid]       = __ldg(src + tid);
        ((float4*)Mt_sh)[tid + 256] = __ldg(src + tid + 256);
    }
    if (tid < Hc) ct_sh[tid] = __ldg(&g_ct[tid]);

    // a[rl][k2] = ca[k2] + x[src]·M_s[k2]  (2 rows per thread)
    {
        int k2 = tid & 127, rr = tid >> 7;
        const float4* ms = (const float4*)(g_Ms + k2 * 16);
        float4 mv[4] = { __ldg(ms), __ldg(ms+1), __ldg(ms+2), __ldg(ms+3) };
        float cav = __ldg(&g_ca[k2]);
        #pragma unroll
        for (int rp = 0; rp < 2; rp++) {
            int rl = rr + rp * 2;
            const float4* xr = (const float4*)(x_sh + (g * 4 + rl) * Fc);
            float4 xv[4] = { xr[0], xr[1], xr[2], xr[3] };
            a_sh[rl][k2] = cav + dot16v(xv, mv);
        }
    }

    // lp: warps 0..3 reduce node rows vs wvec, cb (Wp·bgcn) folded inline
    if (w < 4) {
        int h4 = lane * 4;
        float4 n  = *(const float4*)&u.pre.node[w][h4];
        float4 q  = __ldg((const float4*)(g_wvec + h4));
        float4 wp = __ldg((const float4*)(Wp    + h4));
        float4 bc = __ldg((const float4*)(bgcn  + h4));
        float p0 = n.x*q.x + wp.x*bc.x, p1 = n.y*q.y + wp.y*bc.y;
        float p2 = n.z*q.z + wp.z*bc.z, p3 = n.w*q.w + wp.w*bc.w;
        float v = (p0 + p1) + (p2 + p3);
        #pragma unroll
        for (int o = 16; o; o >>= 1) v += __shfl_xor_sync(0xffffffffu, v, o);
        if (lane == 0) lp_sh[w] = v;
    }
    __syncthreads();   // a_sh, lp_sh, Mt_sh, ct_sh ready; node region now free

    // bt[k][t] for all t: warp w owns kq = w*4..w*4+3
    {
        #pragma unroll
        for (int kk = 0; kk < 4; kk++) {
            int kq = w * 4 + kk;
            float4 mt[4][4];
            float ctv[4];
            #pragma unroll
            for (int c = 0; c < 4; c++) {
                const float4* mr = (const float4*)(Mt_sh + (kq * 4 + c) * Fc);
                mt[c][0] = mr[0]; mt[c][1] = mr[1];
                mt[c][2] = mr[2]; mt[c][3] = mr[3];
                ctv[c] = ct_sh[kq * 4 + c];
            }
            #pragma unroll
            for (int th = 0; th < 2; th++) {
                float4 r;
                r.x = ctv[0] + dot16v(xa[th], mt[0]);
                r.y = ctv[1] + dot16v(xa[th], mt[1]);
                r.z = ctv[2] + dot16v(xa[th], mt[2]);
                r.w = ctv[3] + dot16v(xa[th], mt[3]);
                *(float4*)&u.bt4[kq][th * 32 + lane][0] = r;
            }
        }
    }
    __syncthreads();

    // dense edge loop: warp = (sl = w>>1, th = w&1); lane -> t; 2 accums
    {
        const int sl = w >> 1;
        const int t  = (w & 1) * 32 + lane;
        const int s  = g * 4 + sl;
        const float b2v = __ldg(b2);

        float acc0 = 0.f, acc1 = 0.f;
        #pragma unroll 16
        for (int kq = 0; kq < 32; kq++) {
            float4 a4 = *(const float4*)&a_sh[sl][kq * 4];    // broadcast
            float4 w4 = *(const float4*)&w2_sh[kq * 4];       // broadcast
            float4 bt = *(const float4*)&u.bt4[kq][t][0];     // conflict-free
            acc0 += fmaxf(a4.x + bt.x, 0.f) * w4.x;
            acc1 += fmaxf(a4.y + bt.y, 0.f) * w4.y;
            acc0 += fmaxf(a4.z + bt.z, 0.f) * w4.z;
            acc1 += fmaxf(a4.w + bt.w, 0.f) * w4.w;
        }
        float acc = acc0 + acc1;

        if (t != s) {
            float ew = acc + b2v;
            int e = s * 63 + (t < s ? t : t - 1);
            out[BN + b * E + e] = ew;
            atomicAdd(&pr_sh[t], ew * lp_sh[sl]);
        }
    }
    __syncthreads();
    if (tid < Nc) atomicAdd(out + b * Nc + tid, pr_sh[tid]);
}

// ---------------------------------------------------------------------------
extern "C" void kernel_launch(void* const* d_in, const int* in_sizes, int n_in,
                              void* d_out, int out_size)
{
    const float* x    = (const float*)d_in[0];
    const float* Wg   = (const float*)d_in[2];
    const float* bg   = (const float*)d_in[3];
    const float* W1   = (const float*)d_in[4];
    const float* b1   = (const float*)d_in[5];
    const float* W2   = (const float*)d_in[6];
    const float* b2   = (const float*)d_in[7];
    const float* Wgcn = (const float*)d_in[8];
    const float* bgcn = (const float*)d_in[9];
    const float* Wp   = (const float*)d_in[14];
    const float* bp   = (const float*)d_in[15];
    float* out = (float*)d_out;

    const int E = in_sizes[1] / 2;   // 4032 = 64*63 (dense permutations)

    kfused<<<GRID, NTHR>>>(x, Wg, bg, W1, b1, W2, b2,
                           Wgcn, bgcn, Wp, bp, out, E);
}

// round 17
// speedup vs baseline: 1.0025x; 1.0025x over previous
#include <cuda_runtime.h>

// Problem constants (STGNN_91242285236402): B=8, T=16, N=64, F=16, H=128
#define Bc 8
#define Tc 16
#define Nc 64
#define Fc 16
#define Hc 128
#define BN (Bc * Nc)   // 512
#define GRID 128
#define NTHR 256

// Folded-weight scratch (allocation-free, 16B-aligned for float4 loads)
__device__ __align__(16) float g_Ms[Hc * Fc];   // M_s[k][f] = sum_h W1s[k][h]*Wg[h][f]
__device__ __align__(16) float g_Mt[Hc * Fc];   // M_t[k][f] = sum_h W1t[k][h]*Wg[h][f]
__device__ __align__(16) float g_ca[Hc];        // b1[k] + W1s[k]·bg
__device__ __align__(16) float g_ct[Hc];        // W1t[k]·bg
__device__ __align__(16) float g_wvec[Hc];      // Wgcn.T @ Wp
__device__ unsigned g_bar = 0;                  // grid barrier (monotonic, replay-safe)

__device__ __forceinline__ float dot16v(const float4* a, const float4* b)
{
    float p0 = a[0].x*b[0].x + a[0].y*b[0].y + a[0].z*b[0].z + a[0].w*b[0].w;
    float p1 = a[1].x*b[1].x + a[1].y*b[1].y + a[1].z*b[1].z + a[1].w*b[1].w;
    float p2 = a[2].x*b[2].x + a[2].y*b[2].y + a[2].z*b[2].z + a[2].w*b[2].w;
    float p3 = a[3].x*b[3].x + a[3].y*b[3].y + a[3].z*b[3].z + a[3].w*b[3].w;
    return (p0 + p1) + (p2 + p3);
}

// ---------------------------------------------------------------------------
// One fused kernel, 128 blocks x 256 threads (all co-resident).
// PRE-arrive (block i): stage x[b]; compute row k=i of M_s/M_t (+ca/ct/wvec).
// ARRIVE: single-counter monotonic ticket (the ONLY proven sync pattern).
// HIDDEN: node rows (lp input); w2 stage; pr init; xa register preload.
// WAIT: spin on the SAME counter to wave target; acquire.
// POST (b=i>>4, g=i&15): a from g_Ms; lp from g_wvec;
//   bt[k][t] for all t computed locally, reading g_Mt/g_ct DIRECTLY from L2
//   (no smem staging) -> bt4 smem; dense edge loop:
//     ew(s,t) = b2 + sum_k relu(a[s,k]+bt[k,t])*W2[k], e = s*63+(t-(t>s))
//     pressures[b,t] += ew*lp[s]
// ---------------------------------------------------------------------------
__global__ void __launch_bounds__(NTHR, 1) kfused(
    const float* __restrict__ x,   const float* __restrict__ Wg,
    const float* __restrict__ bg,  const float* __restrict__ W1,
    const float* __restrict__ b1,  const float* __restrict__ W2,
    const float* __restrict__ b2,  const float* __restrict__ Wgcn,
    const float* __restrict__ bgcn,const float* __restrict__ Wp,
    const float* __restrict__ bp,  float* __restrict__ out, int E)
{
    __shared__ union {
        float bt4[32][Nc][4];                 // [k>>2][t][k&3]  (32KB, post)
        struct {
            float pm[2][8][17];               // M partials (padded)
            float node[4][Hc];                // node rows for lp
        } pre;
    } u;
    __shared__ float x_sh[Nc * Fc];           // 4KB  [n][f]
    __shared__ float a_sh[4][Hc];             // 2KB
    __shared__ float w2_sh[Hc];
    __shared__ float lp_sh[4];
    __shared__ float pr_sh[Nc];
    __shared__ unsigned s_target;

    const int tid = threadIdx.x;
    const int i = blockIdx.x;
    const int b = i >> 4, g = i & 15;
    const int k = i;                          // this block's M row
    const int lane = tid & 31, w = tid >> 5;

    // ================= PRE-ARRIVE =================
    // stage x[b, T-1] (256 float4, coalesced)
    {
        const float4* xs = (const float4*)(x + (size_t)((b * Tc + (Tc - 1)) * Nc) * Fc);
        ((float4*)x_sh)[tid] = __ldg(xs + tid);
    }
    if (i < Bc && tid < Nc) out[i * Nc + tid] = __ldg(bp);   // pressures init

    // M partials: side = tid>>7, f = tid&15, hg = (tid>>4)&7 ; W1 via float4
    {
        const int side = tid >> 7;
        const int f = tid & 15;
        const int hg = (tid >> 4) & 7;
        const float4* w1r4 = (const float4*)(W1 + k * (2 * Hc) + side * Hc + hg * 16);
        float4 wa = __ldg(w1r4 + 0), wb = __ldg(w1r4 + 1);
        float4 wc = __ldg(w1r4 + 2), wd = __ldg(w1r4 + 3);
        const float* wgp = Wg + (hg * 16) * Fc + f;
        float s0 = wa.x*__ldg(wgp+ 0*Fc) + wa.y*__ldg(wgp+ 1*Fc)
                 + wa.z*__ldg(wgp+ 2*Fc) + wa.w*__ldg(wgp+ 3*Fc);
        float s1 = wb.x*__ldg(wgp+ 4*Fc) + wb.y*__ldg(wgp+ 5*Fc)
                 + wb.z*__ldg(wgp+ 6*Fc) + wb.w*__ldg(wgp+ 7*Fc);
        float s2 = wc.x*__ldg(wgp+ 8*Fc) + wc.y*__ldg(wgp+ 9*Fc)
                 + wc.z*__ldg(wgp+10*Fc) + wc.w*__ldg(wgp+11*Fc);
        float s3 = wd.x*__ldg(wgp+12*Fc) + wd.y*__ldg(wgp+13*Fc)
                 + wd.z*__ldg(wgp+14*Fc) + wd.w*__ldg(wgp+15*Fc);
        u.pre.pm[side][hg][f] = (s0 + s1) + (s2 + s3);
    }
    __syncthreads();

    // finishing: warp0 M-reduce; warp2 ca/ct; warp3 wvec[k]
    if (w == 0) {
        int side = lane >> 4, f = lane & 15;
        float m = 0.f;
        #pragma unroll
        for (int hg = 0; hg < 8; hg++) m += u.pre.pm[side][hg][f];
        if (side == 0) g_Ms[k * 16 + f] = m;
        else           g_Mt[k * 16 + f] = m;
    } else if (w == 2) {
        int side = lane >> 4;
        int h0 = (lane & 15) * 8;
        const float* w1r = W1 + k * (2 * Hc) + side * Hc + h0;
        float s = 0.f;
        #pragma unroll
        for (int e = 0; e < 8; e++) s += __ldg(&bg[h0 + e]) * __ldg(w1r + e);
        s += __shfl_xor_sync(0xffffffffu, s, 1);
        s += __shfl_xor_sync(0xffffffffu, s, 2);
        s += __shfl_xor_sync(0xffffffffu, s, 4);
        s += __shfl_xor_sync(0xffffffffu, s, 8);
        if ((lane & 15) == 0) {
            if (side == 0) g_ca[k] = s + __ldg(&b1[k]);
            else           g_ct[k] = s;
        }
    } else if (w == 3) {
        float s = 0.f;
        #pragma unroll
        for (int e = 0; e < 4; e++)
            s += __ldg(&Wp[lane * 4 + e]) * __ldg(&Wgcn[(lane * 4 + e) * Hc + k]);
        #pragma unroll
        for (int o = 16; o; o >>= 1) s += __shfl_xor_sync(0xffffffffu, s, o);
        if (lane == 0) g_wvec[k] = s;
    }

    // ---- ARRIVE (single-counter monotonic ticket — the proven pattern)
    __syncthreads();                          // all cross-block stores issued
    if (tid == 0) {
        __threadfence();                      // publish before arrival
        unsigned v = atomicAdd(&g_bar, 1u);
        s_target = (v & ~(GRID - 1u)) + GRID;
    }

    // ======== HIDDEN independent work (between arrive and wait) ========
    // node rows (for lp): 4 rows x 128 h, 2 outputs/thread
    #pragma unroll
    for (int it = 0; it < 2; it++) {
        int idx = tid + it * NTHR;
        int rl = idx >> 7, h = idx & 127;
        const float4* wg4 = (const float4*)(Wg + h * Fc);
        float4 wv[4] = { __ldg(wg4), __ldg(wg4+1), __ldg(wg4+2), __ldg(wg4+3) };
        const float4* xr = (const float4*)(x_sh + (g * 4 + rl) * Fc);
        float4 xv[4] = { xr[0], xr[1], xr[2], xr[3] };
        u.pre.node[rl][h] = __ldg(&bg[h]) + dot16v(xv, wv);
    }
    if (tid < Hc) w2_sh[tid] = __ldg(&W2[tid]);
    if (tid < Nc) pr_sh[tid] = 0.f;
    // xa preload for bt phase (persists in registers across the wait)
    float4 xa[2][4];
    #pragma unroll
    for (int th = 0; th < 2; th++)
        #pragma unroll
        for (int jj = 0; jj < 4; jj++)
            xa[th][jj] = *(const float4*)(x_sh + (th * 32 + lane) * Fc + jj * 4);

    // ---- WAIT: spin on the SAME counter (proven)
    __syncthreads();                          // s_target visible; hidden done
    if (tid == 0) {
        volatile unsigned* p = &g_bar;
        while (*p < s_target) __nanosleep(32);
        __threadfence();                      // acquire
    }
    __syncthreads();

    // ================= POST =================
    // a[rl][k2] = ca[k2] + x[src]·M_s[k2]  (2 rows per thread), direct L2
    {
        int k2 = tid & 127, rr = tid >> 7;
        const float4* ms = (const float4*)(g_Ms + k2 * 16);
        float4 mv[4] = { __ldg(ms), __ldg(ms+1), __ldg(ms+2), __ldg(ms+3) };
        float cav = __ldg(&g_ca[k2]);
        #pragma unroll
        for (int rp = 0; rp < 2; rp++) {
            int rl = rr + rp * 2;
            const float4* xr = (const float4*)(x_sh + (g * 4 + rl) * Fc);
            float4 xv[4] = { xr[0], xr[1], xr[2], xr[3] };
            a_sh[rl][k2] = cav + dot16v(xv, mv);
        }
    }

    // lp: warps 0..3 reduce node rows vs wvec, cb (Wp·bgcn) folded inline
    if (w < 4) {
        int h4 = lane * 4;
        float4 n  = *(const float4*)&u.pre.node[w][h4];
        float4 q  = __ldg((const float4*)(g_wvec + h4));
        float4 wp = __ldg((const float4*)(Wp    + h4));
        float4 bc = __ldg((const float4*)(bgcn  + h4));
        float p0 = n.x*q.x + wp.x*bc.x, p1 = n.y*q.y + wp.y*bc.y;
        float p2 = n.z*q.z + wp.z*bc.z, p3 = n.w*q.w + wp.w*bc.w;
        float v = (p0 + p1) + (p2 + p3);
        #pragma unroll
        for (int o = 16; o; o >>= 1) v += __shfl_xor_sync(0xffffffffu, v, o);
        if (lane == 0) lp_sh[w] = v;
    }
    __syncthreads();   // a_sh, lp_sh ready; node region now free for bt4

    // bt[k][t] for all t: warp w owns kq = w*4..w*4+3.
    // M_t/ct read DIRECTLY from global (L2-resident 8KB, no smem staging).
    {
        #pragma unroll
        for (int kk = 0; kk < 4; kk++) {
            int kq = w * 4 + kk;
            float4 mt[4][4];
            float ctv[4];
            #pragma unroll
            for (int c = 0; c < 4; c++) {
                const float4* mr = (const float4*)(g_Mt + (kq * 4 + c) * Fc);
                mt[c][0] = __ldg(mr + 0); mt[c][1] = __ldg(mr + 1);
                mt[c][2] = __ldg(mr + 2); mt[c][3] = __ldg(mr + 3);
                ctv[c] = __ldg(&g_ct[kq * 4 + c]);
            }
            #pragma unroll
            for (int th = 0; th < 2; th++) {
                float4 r;
                r.x = ctv[0] + dot16v(xa[th], mt[0]);
                r.y = ctv[1] + dot16v(xa[th], mt[1]);
                r.z = ctv[2] + dot16v(xa[th], mt[2]);
                r.w = ctv[3] + dot16v(xa[th], mt[3]);
                *(float4*)&u.bt4[kq][th * 32 + lane][0] = r;
            }
        }
    }
    __syncthreads();

    // dense edge loop: warp = (sl = w>>1, th = w&1); lane -> t; 2 accums
    {
        const int sl = w >> 1;
        const int t  = (w & 1) * 32 + lane;
        const int s  = g * 4 + sl;
        const float b2v = __ldg(b2);

        float acc0 = 0.f, acc1 = 0.f;
        #pragma unroll 16
        for (int kq = 0; kq < 32; kq++) {
            float4 a4 = *(const float4*)&a_sh[sl][kq * 4];    // broadcast
            float4 w4 = *(const float4*)&w2_sh[kq * 4];       // broadcast
            float4 bt = *(const float4*)&u.bt4[kq][t][0];     // conflict-free
            acc0 += fmaxf(a4.x + bt.x, 0.f) * w4.x;
            acc1 += fmaxf(a4.y + bt.y, 0.f) * w4.y;
            acc0 += fmaxf(a4.z + bt.z, 0.f) * w4.z;
            acc1 += fmaxf(a4.w + bt.w, 0.f) * w4.w;
        }
        float acc = acc0 + acc1;

        if (t != s) {
            float ew = acc + b2v;
            int e = s * 63 + (t < s ? t : t - 1);
            out[BN + b * E + e] = ew;
            atomicAdd(&pr_sh[t], ew * lp_sh[sl]);
        }
    }
    __syncthreads();
    if (tid < Nc) atomicAdd(out + b * Nc + tid, pr_sh[tid]);
}

// ---------------------------------------------------------------------------
extern "C" void kernel_launch(void* const* d_in, const int* in_sizes, int n_in,
                              void* d_out, int out_size)
{
    const float* x    = (const float*)d_in[0];
    const float* Wg   = (const float*)d_in[2];
    const float* bg   = (const float*)d_in[3];
    const float* W1   = (const float*)d_in[4];
    const float* b1   = (const float*)d_in[5];
    const float* W2   = (const float*)d_in[6];
    const float* b2   = (const float*)d_in[7];
    const float* Wgcn = (const float*)d_in[8];
    const float* bgcn = (const float*)d_in[9];
    const float* Wp   = (const float*)d_in[14];
    const float* bp   = (const float*)d_in[15];
    float* out = (float*)d_out;

    const int E = in_sizes[1] / 2;   // 4032 = 64*63 (dense permutations)

    kfused<<<GRID, NTHR>>>(x, Wg, bg, W1, b1, W2, b2,
                           Wgcn, bgcn, Wp, bp, out, E);
}